// round 15
// baseline (speedup 1.0000x reference)
#include <cuda_runtime.h>
#include <cuda_fp16.h>
#include <cstdint>
#include <cstddef>

// ============================================================================
// TurboQuantLinear: out[t,n] = sum_k x[t,k] * W_eff[n,k]
//   W_eff[n, g*128+k] = (norms[n,g]/sqrt(128)) * sum_j codes[n,g,j]*R[g,j,k]
// sm_100 (no 'a'). ldmatrix + mma.sync m16n8k16 fp16->fp32.
// R15: instruction-level interleave of ldsm and MMA inside each kk step
// (asm volatile order is literal), and MMAs queued before the per-kt
// barrier to cover arrival skew. Shape = R14 (2 CTAs/SM, 64x32 warp tile,
// BK=64, 3 stages, rolling pointers) — measured gemm 672.8us, tensor 78.6%.
// ============================================================================

constexpr int TOKENS = 8192;
constexpr int KDIM   = 4096;
constexpr int NDIM   = 4096;
constexpr float INV_SCALE = 0.08838834764831845f; // 1/sqrt(128)

__device__ __align__(16) __half g_xh[(size_t)TOKENS * KDIM];   // 64 MB
__device__ __align__(16) __half g_wh[(size_t)NDIM * KDIM];     // 32 MB
__device__ __align__(16) __half g_rt[(size_t)32 * 128 * 128];  // 1 MB, Rt[g][k][j]

// ---- PTX helpers -----------------------------------------------------------
__device__ __forceinline__ uint32_t smem_u32(const void* p) {
    uint32_t a;
    asm("{ .reg .u64 t; cvta.to.shared.u64 t, %1; cvt.u32.u64 %0, t; }"
        : "=r"(a) : "l"(p));
    return a;
}
__device__ __forceinline__ void cp16(uint32_t s, const void* g) {
    asm volatile("cp.async.cg.shared.global [%0], [%1], 16;" :: "r"(s), "l"(g));
}
#define CP_COMMIT() asm volatile("cp.async.commit_group;" ::: "memory")
#define CP_WAIT(n)  asm volatile("cp.async.wait_group %0;" :: "n"(n) : "memory")

__device__ __forceinline__ void ldsm_x4(uint32_t (&r)[4], uint32_t addr) {
    asm volatile("ldmatrix.sync.aligned.m8n8.x4.shared.b16 {%0,%1,%2,%3}, [%4];"
        : "=r"(r[0]), "=r"(r[1]), "=r"(r[2]), "=r"(r[3]) : "r"(addr));
}
__device__ __forceinline__ void mma16816(float (&d)[4], const uint32_t (&a)[4],
                                         uint32_t b0, uint32_t b1) {
    asm volatile("mma.sync.aligned.m16n8k16.row.col.f32.f16.f16.f32 "
        "{%0,%1,%2,%3}, {%4,%5,%6,%7}, {%8,%9}, {%0,%1,%2,%3};"
        : "+f"(d[0]), "+f"(d[1]), "+f"(d[2]), "+f"(d[3])
        : "r"(a[0]), "r"(a[1]), "r"(a[2]), "r"(a[3]), "r"(b0), "r"(b1));
}
__device__ __forceinline__ uint32_t pack_h2(__half a, __half b) {
    return (uint32_t)__half_as_ushort(a) | ((uint32_t)__half_as_ushort(b) << 16);
}

// ---------------------------------------------------------------------------
// Kernel 1: x fp32 -> fp16
// ---------------------------------------------------------------------------
__global__ void __launch_bounds__(256) convert_x_kernel(const float4* __restrict__ x) {
    size_t i = (size_t)blockIdx.x * blockDim.x + threadIdx.x;
    float4 v = x[i];
    uint2 p;
    p.x = pack_h2(__float2half_rn(v.x), __float2half_rn(v.y));
    p.y = pack_h2(__float2half_rn(v.z), __float2half_rn(v.w));
    *(uint2*)(g_xh + 4 * i) = p;
}

// ---------------------------------------------------------------------------
// Kernel 2a: Rt[g][k][j] = fp16(rot[g][j][k]). One block per group.
// ---------------------------------------------------------------------------
__global__ void __launch_bounds__(256) transpose_r_kernel(const float* __restrict__ rot) {
    extern __shared__ float rs[];           // 128*129 floats = 66048 B
    const int t = threadIdx.x;
    const int g = blockIdx.x;
    const float* rg = rot + (size_t)g * 16384;
#pragma unroll 16
    for (int it = 0; it < 64; it++) {
        int idx = t + 256 * it;             // j*128 + k
        rs[(idx >> 7) * 129 + (idx & 127)] = rg[idx];
    }
    __syncthreads();
    __half* og = g_rt + (size_t)g * 16384;
#pragma unroll 16
    for (int it = 0; it < 64; it++) {
        int idx = t + 256 * it;             // k*128 + j
        int k = idx >> 7, j = idx & 127;
        og[idx] = __float2half_rn(rs[j * 129 + k]);
    }
}

// ---------------------------------------------------------------------------
// Kernel 2b: prep on tensor cores (unchanged; measured fast).
// ---------------------------------------------------------------------------
constexpr int PROWB = 272;
constexpr int PTILE = 128 * PROWB;          // 34816
constexpr int PREP_SMEM = 2 * PTILE;        // 69632

__global__ void __launch_bounds__(256, 1) prep_mma_kernel(
        const int* __restrict__ packed, const float* __restrict__ cb,
        const float* __restrict__ norms) {
    extern __shared__ __align__(128) char psm[];
    __shared__ float cbs[16];
    __shared__ float snorm[128];
    const uint32_t sb = smem_u32(psm);
    const int t = threadIdx.x, lid = t & 31, wid = t >> 5;
    const int g = blockIdx.y;
    const int row0 = blockIdx.x * 128;

    if (t < 16) cbs[t] = cb[t];
    if (t < 128) snorm[t] = norms[(size_t)(row0 + t) * 32 + g] * INV_SCALE;

#pragma unroll
    for (int p = 0; p < 8; p++) {
        int ch = t + 256 * p; int r = ch >> 4, c = ch & 15;
        cp16(sb + PTILE + (uint32_t)(r * PROWB + c * 16),
             g_rt + (size_t)g * 16384 + r * 128 + c * 8);
    }
    CP_COMMIT();
    __syncthreads();

#pragma unroll 8
    for (int it = 0; it < 32; it++) {
        int idx = t + 256 * it;
        int r = idx >> 6, ii = idx & 63;
        int v = packed[(size_t)(row0 + r) * 2048 + g * 64 + ii] & 0xFF;
        *(uint32_t*)(psm + r * PROWB + ii * 4) =
            pack_h2(__float2half_rn(cbs[v & 0xF]), __float2half_rn(cbs[(v >> 4) & 0xF]));
    }
    CP_WAIT(0);
    __syncthreads();

    const int wm = wid & 1, wn = wid >> 1;
    const int rsel = lid & 15, csel = lid >> 4;

    float acc[4][4][4];
#pragma unroll
    for (int mi = 0; mi < 4; mi++)
#pragma unroll
        for (int ni = 0; ni < 4; ni++)
#pragma unroll
            for (int q = 0; q < 4; q++) acc[mi][ni][q] = 0.f;

#pragma unroll
    for (int k16 = 0; k16 < 8; k16++) {
        uint32_t a[4][4], b[2][4];
        const uint32_t kadd = (uint32_t)(k16 * 32 + csel * 16);
#pragma unroll
        for (int mi = 0; mi < 4; mi++)
            ldsm_x4(a[mi], sb + (wm * 64 + mi * 16 + rsel) * PROWB + kadd);
#pragma unroll
        for (int nh = 0; nh < 2; nh++)
            ldsm_x4(b[nh], sb + PTILE + (wn * 32 + nh * 16 + rsel) * PROWB + kadd);
#pragma unroll
        for (int mi = 0; mi < 4; mi++)
#pragma unroll
            for (int ni = 0; ni < 4; ni++) {
                const int nh = ni >> 1, s2 = ni & 1;
                mma16816(acc[mi][ni], a[mi], b[nh][s2], b[nh][s2 + 2]);
            }
    }

    const int r0 = lid >> 2, c0 = (lid & 3) * 2;
#pragma unroll
    for (int mi = 0; mi < 4; mi++) {
        const int mloc = wm * 64 + mi * 16 + r0;
        const float s0 = snorm[mloc], s1 = snorm[mloc + 8];
#pragma unroll
        for (int ni = 0; ni < 4; ni++) {
            const int kout = wn * 32 + ni * 8 + c0;
            size_t o = (size_t)(row0 + mloc) * 4096 + g * 128 + kout;
            *(uint32_t*)(g_wh + o) =
                pack_h2(__float2half_rn(acc[mi][ni][0] * s0),
                        __float2half_rn(acc[mi][ni][1] * s0));
            *(uint32_t*)(g_wh + o + 8 * 4096) =
                pack_h2(__float2half_rn(acc[mi][ni][2] * s1),
                        __float2half_rn(acc[mi][ni][3] * s1));
        }
    }
}

// ---------------------------------------------------------------------------
// Kernel 3: GEMM. BM=128 BN=128 BK=64, 3 stages, 256 threads (8 warps, 2x4),
// warp tile 64x32, 2 CTAs/SM, frag double-buffering, rolling load pointers,
// fine-grained ldsm/MMA interleave.
// ---------------------------------------------------------------------------
constexpr int STAGES = 3;
constexpr int ROWB   = 144;
constexpr int ATILEB = 128 * ROWB;          // 18432
constexpr int BTILEB = 128 * ROWB;          // 18432
constexpr int STG    = ATILEB + BTILEB;     // 36864
constexpr int GEMM_SMEM = STAGES * STG;     // 110592  (x2 CTAs = 221184)

__global__ void __launch_bounds__(256, 2) gemm_kernel(float* __restrict__ out) {
    extern __shared__ __align__(128) char smem[];
    const uint32_t sb = smem_u32(smem);
    const int tid = threadIdx.x, lid = tid & 31, wid = tid >> 5;
    const int wm = wid & 1, wn = wid >> 1;          // 2 (M) x 4 (N)
    const size_t m0 = (size_t)blockIdx.x * 128;
    const size_t n0 = (size_t)blockIdx.y * 128;

    float acc[4][4][4];
#pragma unroll
    for (int mi = 0; mi < 4; mi++)
#pragma unroll
        for (int ni = 0; ni < 4; ni++)
#pragma unroll
            for (int q = 0; q < 4; q++) acc[mi][ni][q] = 0.f;

    // rolling cp.async state
    const int lr = tid >> 3, lc = tid & 7;
    const __half* pa = g_xh + (m0 + lr) * 4096 + lc * 8;
    const __half* pb = g_wh + (n0 + lr) * 4096 + lc * 8;
    const uint32_t sA = sb + (uint32_t)(lr * ROWB + lc * 16);
    int slot = 0;
    int remaining = 64;

    auto issue = [&]() {
        if (remaining > 0) {
            const uint32_t st = sA + (uint32_t)slot * STG;
#pragma unroll
            for (int p = 0; p < 4; p++)
                cp16(st + p * (32 * ROWB), pa + (size_t)p * (32 * 4096));
#pragma unroll
            for (int p = 0; p < 4; p++)
                cp16(st + ATILEB + p * (32 * ROWB), pb + (size_t)p * (32 * 4096));
            pa += 64; pb += 64;
            remaining--;
        }
        CP_COMMIT();
        slot = (slot == STAGES - 1) ? 0 : slot + 1;
    };

    issue();        // stage 0
    issue();        // stage 1

    const int rsel = lid & 15, csel = lid >> 4;
    uint32_t aoff[4], boff[2];
#pragma unroll
    for (int mi = 0; mi < 4; mi++)
        aoff[mi] = (uint32_t)((wm * 64 + mi * 16 + rsel) * ROWB + csel * 16);
#pragma unroll
    for (int nh = 0; nh < 2; nh++)
        boff[nh] = (uint32_t)(ATILEB + (wn * 32 + nh * 16 + rsel) * ROWB + csel * 16);

    CP_WAIT(1);
    __syncthreads();

    uint32_t a[2][4][4], b[2][2][4];        // double-buffered fragments
    {
        const uint32_t st0 = sb;            // stage 0
#pragma unroll
        for (int mi = 0; mi < 4; mi++) ldsm_x4(a[0][mi], st0 + aoff[mi]);
#pragma unroll
        for (int nh = 0; nh < 2; nh++) ldsm_x4(b[0][nh], st0 + boff[nh]);
    }

    // one MMA row (4 MMAs) on buffer `buf`, row mi — order identical to R14
#define MMA_ROW(buf, mi)                                                     \
    do {                                                                     \
        mma16816(acc[mi][0], a[buf][mi], b[buf][0][0], b[buf][0][2]);        \
        mma16816(acc[mi][1], a[buf][mi], b[buf][0][1], b[buf][0][3]);        \
        mma16816(acc[mi][2], a[buf][mi], b[buf][1][0], b[buf][1][2]);        \
        mma16816(acc[mi][3], a[buf][mi], b[buf][1][1], b[buf][1][3]);        \
    } while (0)

    for (int kt = 0; kt < 64; kt++) {
        const uint32_t st  = sb + (kt % STAGES) * STG;
        const uint32_t stn = sb + ((kt + 1) % STAGES) * STG;
        issue();                            // stage kt+2 -> slot (kt-1)%3
#pragma unroll
        for (int kk = 0; kk < 3; kk++) {    // cur = kk&1, nxt = !cur
            const int cur = kk & 1, nxt = cur ^ 1;
            const uint32_t kadd = (uint32_t)((kk + 1) * 32);
            // interleave prefetch-ldsm (nxt) with MMAs (cur)
            ldsm_x4(a[nxt][0], st + aoff[0] + kadd);
            ldsm_x4(a[nxt][1], st + aoff[1] + kadd);
            MMA_ROW(cur, 0);
            ldsm_x4(a[nxt][2], st + aoff[2] + kadd);
            ldsm_x4(a[nxt][3], st + aoff[3] + kadd);
            MMA_ROW(cur, 1);
            ldsm_x4(b[nxt][0], st + boff[0] + kadd);
            MMA_ROW(cur, 2);
            ldsm_x4(b[nxt][1], st + boff[1] + kadd);
            MMA_ROW(cur, 3);
        }
        {   // kk == 3: cur = 1, nxt = 0; queue MMAs before the barrier
            MMA_ROW(1, 0);
            MMA_ROW(1, 1);
            CP_WAIT(1);                     // stage kt+1 resident
            __syncthreads();
            ldsm_x4(a[0][0], stn + aoff[0]);
            ldsm_x4(a[0][1], stn + aoff[1]);
            ldsm_x4(a[0][2], stn + aoff[2]);
            MMA_ROW(1, 2);
            ldsm_x4(a[0][3], stn + aoff[3]);
            ldsm_x4(b[0][0], stn + boff[0]);
            ldsm_x4(b[0][1], stn + boff[1]);
            MMA_ROW(1, 3);
        }
    }
#undef MMA_ROW

    const int r0 = lid >> 2, c0 = (lid & 3) * 2;
#pragma unroll
    for (int mi = 0; mi < 4; mi++)
#pragma unroll
        for (int ni = 0; ni < 4; ni++) {
            size_t m = m0 + wm * 64 + mi * 16 + r0;
            size_t n = n0 + wn * 32 + ni * 8 + c0;
            *(float2*)(out + m * 4096 + n) =
                make_float2(acc[mi][ni][0], acc[mi][ni][1]);
            *(float2*)(out + (m + 8) * 4096 + n) =
                make_float2(acc[mi][ni][2], acc[mi][ni][3]);
        }
}

// ---------------------------------------------------------------------------
extern "C" void kernel_launch(void* const* d_in, const int* in_sizes, int n_in,
                              void* d_out, int out_size) {
    const float* x      = (const float*)d_in[0];
    const int*   packed = (const int*)  d_in[1];
    const float* cb     = (const float*)d_in[2];
    const float* norms  = (const float*)d_in[3];
    const float* rot    = (const float*)d_in[4];
    float* out = (float*)d_out;

    cudaFuncSetAttribute(transpose_r_kernel, cudaFuncAttributeMaxDynamicSharedMemorySize, 66048);
    cudaFuncSetAttribute(prep_mma_kernel,   cudaFuncAttributeMaxDynamicSharedMemorySize, PREP_SMEM);
    cudaFuncSetAttribute(gemm_kernel,       cudaFuncAttributeMaxDynamicSharedMemorySize, GEMM_SMEM);

    convert_x_kernel<<<32768, 256>>>((const float4*)x);
    transpose_r_kernel<<<32, 256, 66048>>>(rot);
    prep_mma_kernel<<<dim3(32, 32), 256, PREP_SMEM>>>(packed, cb, norms);
    gemm_kernel<<<dim3(64, 32), 256, GEMM_SMEM>>>(out);
}

// round 16
// speedup vs baseline: 1.1489x; 1.1489x over previous
#include <cuda_runtime.h>
#include <cuda_fp16.h>
#include <cstdint>
#include <cstddef>

// ============================================================================
// TurboQuantLinear: out[t,n] = sum_k x[t,k] * W_eff[n,k]
//   W_eff[n, g*128+k] = (norms[n,g]/sqrt(128)) * sum_j codes[n,g,j]*R[g,j,k]
// sm_100 (no 'a'). ldmatrix + mma.sync m16n8k16 fp16->fp32.
// R16: exact R14 mainloop (best: gemm 672.8us, tensor 78.6%; R15's fine
// interleave regressed -> burst ldsm + dense MMA chains are right), with ONE
// delta: at the kt boundary, 8 MMAs are queued BEFORE CP_WAIT/sync so the
// tensor pipe stays fed across the barrier.
// ============================================================================

constexpr int TOKENS = 8192;
constexpr int KDIM   = 4096;
constexpr int NDIM   = 4096;
constexpr float INV_SCALE = 0.08838834764831845f; // 1/sqrt(128)

__device__ __align__(16) __half g_xh[(size_t)TOKENS * KDIM];   // 64 MB
__device__ __align__(16) __half g_wh[(size_t)NDIM * KDIM];     // 32 MB
__device__ __align__(16) __half g_rt[(size_t)32 * 128 * 128];  // 1 MB, Rt[g][k][j]

// ---- PTX helpers -----------------------------------------------------------
__device__ __forceinline__ uint32_t smem_u32(const void* p) {
    uint32_t a;
    asm("{ .reg .u64 t; cvta.to.shared.u64 t, %1; cvt.u32.u64 %0, t; }"
        : "=r"(a) : "l"(p));
    return a;
}
__device__ __forceinline__ void cp16(uint32_t s, const void* g) {
    asm volatile("cp.async.cg.shared.global [%0], [%1], 16;" :: "r"(s), "l"(g));
}
#define CP_COMMIT() asm volatile("cp.async.commit_group;" ::: "memory")
#define CP_WAIT(n)  asm volatile("cp.async.wait_group %0;" :: "n"(n) : "memory")

__device__ __forceinline__ void ldsm_x4(uint32_t (&r)[4], uint32_t addr) {
    asm volatile("ldmatrix.sync.aligned.m8n8.x4.shared.b16 {%0,%1,%2,%3}, [%4];"
        : "=r"(r[0]), "=r"(r[1]), "=r"(r[2]), "=r"(r[3]) : "r"(addr));
}
__device__ __forceinline__ void mma16816(float (&d)[4], const uint32_t (&a)[4],
                                         uint32_t b0, uint32_t b1) {
    asm volatile("mma.sync.aligned.m16n8k16.row.col.f32.f16.f16.f32 "
        "{%0,%1,%2,%3}, {%4,%5,%6,%7}, {%8,%9}, {%0,%1,%2,%3};"
        : "+f"(d[0]), "+f"(d[1]), "+f"(d[2]), "+f"(d[3])
        : "r"(a[0]), "r"(a[1]), "r"(a[2]), "r"(a[3]), "r"(b0), "r"(b1));
}
__device__ __forceinline__ uint32_t pack_h2(__half a, __half b) {
    return (uint32_t)__half_as_ushort(a) | ((uint32_t)__half_as_ushort(b) << 16);
}

// ---------------------------------------------------------------------------
// Kernel 1: x fp32 -> fp16
// ---------------------------------------------------------------------------
__global__ void __launch_bounds__(256) convert_x_kernel(const float4* __restrict__ x) {
    size_t i = (size_t)blockIdx.x * blockDim.x + threadIdx.x;
    float4 v = x[i];
    uint2 p;
    p.x = pack_h2(__float2half_rn(v.x), __float2half_rn(v.y));
    p.y = pack_h2(__float2half_rn(v.z), __float2half_rn(v.w));
    *(uint2*)(g_xh + 4 * i) = p;
}

// ---------------------------------------------------------------------------
// Kernel 2a: Rt[g][k][j] = fp16(rot[g][j][k]). One block per group.
// ---------------------------------------------------------------------------
__global__ void __launch_bounds__(256) transpose_r_kernel(const float* __restrict__ rot) {
    extern __shared__ float rs[];           // 128*129 floats = 66048 B
    const int t = threadIdx.x;
    const int g = blockIdx.x;
    const float* rg = rot + (size_t)g * 16384;
#pragma unroll 16
    for (int it = 0; it < 64; it++) {
        int idx = t + 256 * it;             // j*128 + k
        rs[(idx >> 7) * 129 + (idx & 127)] = rg[idx];
    }
    __syncthreads();
    __half* og = g_rt + (size_t)g * 16384;
#pragma unroll 16
    for (int it = 0; it < 64; it++) {
        int idx = t + 256 * it;             // k*128 + j
        int k = idx >> 7, j = idx & 127;
        og[idx] = __float2half_rn(rs[j * 129 + k]);
    }
}

// ---------------------------------------------------------------------------
// Kernel 2b: prep on tensor cores (unchanged; measured fast).
// ---------------------------------------------------------------------------
constexpr int PROWB = 272;
constexpr int PTILE = 128 * PROWB;          // 34816
constexpr int PREP_SMEM = 2 * PTILE;        // 69632

__global__ void __launch_bounds__(256, 1) prep_mma_kernel(
        const int* __restrict__ packed, const float* __restrict__ cb,
        const float* __restrict__ norms) {
    extern __shared__ __align__(128) char psm[];
    __shared__ float cbs[16];
    __shared__ float snorm[128];
    const uint32_t sb = smem_u32(psm);
    const int t = threadIdx.x, lid = t & 31, wid = t >> 5;
    const int g = blockIdx.y;
    const int row0 = blockIdx.x * 128;

    if (t < 16) cbs[t] = cb[t];
    if (t < 128) snorm[t] = norms[(size_t)(row0 + t) * 32 + g] * INV_SCALE;

#pragma unroll
    for (int p = 0; p < 8; p++) {
        int ch = t + 256 * p; int r = ch >> 4, c = ch & 15;
        cp16(sb + PTILE + (uint32_t)(r * PROWB + c * 16),
             g_rt + (size_t)g * 16384 + r * 128 + c * 8);
    }
    CP_COMMIT();
    __syncthreads();

#pragma unroll 8
    for (int it = 0; it < 32; it++) {
        int idx = t + 256 * it;
        int r = idx >> 6, ii = idx & 63;
        int v = packed[(size_t)(row0 + r) * 2048 + g * 64 + ii] & 0xFF;
        *(uint32_t*)(psm + r * PROWB + ii * 4) =
            pack_h2(__float2half_rn(cbs[v & 0xF]), __float2half_rn(cbs[(v >> 4) & 0xF]));
    }
    CP_WAIT(0);
    __syncthreads();

    const int wm = wid & 1, wn = wid >> 1;
    const int rsel = lid & 15, csel = lid >> 4;

    float acc[4][4][4];
#pragma unroll
    for (int mi = 0; mi < 4; mi++)
#pragma unroll
        for (int ni = 0; ni < 4; ni++)
#pragma unroll
            for (int q = 0; q < 4; q++) acc[mi][ni][q] = 0.f;

#pragma unroll
    for (int k16 = 0; k16 < 8; k16++) {
        uint32_t a[4][4], b[2][4];
        const uint32_t kadd = (uint32_t)(k16 * 32 + csel * 16);
#pragma unroll
        for (int mi = 0; mi < 4; mi++)
            ldsm_x4(a[mi], sb + (wm * 64 + mi * 16 + rsel) * PROWB + kadd);
#pragma unroll
        for (int nh = 0; nh < 2; nh++)
            ldsm_x4(b[nh], sb + PTILE + (wn * 32 + nh * 16 + rsel) * PROWB + kadd);
#pragma unroll
        for (int mi = 0; mi < 4; mi++)
#pragma unroll
            for (int ni = 0; ni < 4; ni++) {
                const int nh = ni >> 1, s2 = ni & 1;
                mma16816(acc[mi][ni], a[mi], b[nh][s2], b[nh][s2 + 2]);
            }
    }

    const int r0 = lid >> 2, c0 = (lid & 3) * 2;
#pragma unroll
    for (int mi = 0; mi < 4; mi++) {
        const int mloc = wm * 64 + mi * 16 + r0;
        const float s0 = snorm[mloc], s1 = snorm[mloc + 8];
#pragma unroll
        for (int ni = 0; ni < 4; ni++) {
            const int kout = wn * 32 + ni * 8 + c0;
            size_t o = (size_t)(row0 + mloc) * 4096 + g * 128 + kout;
            *(uint32_t*)(g_wh + o) =
                pack_h2(__float2half_rn(acc[mi][ni][0] * s0),
                        __float2half_rn(acc[mi][ni][1] * s0));
            *(uint32_t*)(g_wh + o + 8 * 4096) =
                pack_h2(__float2half_rn(acc[mi][ni][2] * s1),
                        __float2half_rn(acc[mi][ni][3] * s1));
        }
    }
}

// ---------------------------------------------------------------------------
// Kernel 3: GEMM. BM=128 BN=128 BK=64, 3 stages, 256 threads (8 warps, 2x4),
// warp tile 64x32, 2 CTAs/SM, frag double-buffering, rolling load pointers.
// R14 burst order inside kk; kt-boundary barrier covered by 8 queued MMAs.
// ---------------------------------------------------------------------------
constexpr int STAGES = 3;
constexpr int ROWB   = 144;
constexpr int ATILEB = 128 * ROWB;          // 18432
constexpr int BTILEB = 128 * ROWB;          // 18432
constexpr int STG    = ATILEB + BTILEB;     // 36864
constexpr int GEMM_SMEM = STAGES * STG;     // 110592  (x2 CTAs = 221184)

__global__ void __launch_bounds__(256, 2) gemm_kernel(float* __restrict__ out) {
    extern __shared__ __align__(128) char smem[];
    const uint32_t sb = smem_u32(smem);
    const int tid = threadIdx.x, lid = tid & 31, wid = tid >> 5;
    const int wm = wid & 1, wn = wid >> 1;          // 2 (M) x 4 (N)
    const size_t m0 = (size_t)blockIdx.x * 128;
    const size_t n0 = (size_t)blockIdx.y * 128;

    float acc[4][4][4];
#pragma unroll
    for (int mi = 0; mi < 4; mi++)
#pragma unroll
        for (int ni = 0; ni < 4; ni++)
#pragma unroll
            for (int q = 0; q < 4; q++) acc[mi][ni][q] = 0.f;

    // rolling cp.async state
    const int lr = tid >> 3, lc = tid & 7;
    const __half* pa = g_xh + (m0 + lr) * 4096 + lc * 8;
    const __half* pb = g_wh + (n0 + lr) * 4096 + lc * 8;
    const uint32_t sA = sb + (uint32_t)(lr * ROWB + lc * 16);
    int slot = 0;
    int remaining = 64;

    auto issue = [&]() {
        if (remaining > 0) {
            const uint32_t st = sA + (uint32_t)slot * STG;
#pragma unroll
            for (int p = 0; p < 4; p++)
                cp16(st + p * (32 * ROWB), pa + (size_t)p * (32 * 4096));
#pragma unroll
            for (int p = 0; p < 4; p++)
                cp16(st + ATILEB + p * (32 * ROWB), pb + (size_t)p * (32 * 4096));
            pa += 64; pb += 64;
            remaining--;
        }
        CP_COMMIT();
        slot = (slot == STAGES - 1) ? 0 : slot + 1;
    };

    issue();        // stage 0
    issue();        // stage 1

    const int rsel = lid & 15, csel = lid >> 4;
    uint32_t aoff[4], boff[2];
#pragma unroll
    for (int mi = 0; mi < 4; mi++)
        aoff[mi] = (uint32_t)((wm * 64 + mi * 16 + rsel) * ROWB + csel * 16);
#pragma unroll
    for (int nh = 0; nh < 2; nh++)
        boff[nh] = (uint32_t)(ATILEB + (wn * 32 + nh * 16 + rsel) * ROWB + csel * 16);

    CP_WAIT(1);
    __syncthreads();

    uint32_t a[2][4][4], b[2][2][4];        // double-buffered fragments
    {
        const uint32_t st0 = sb;            // stage 0
#pragma unroll
        for (int mi = 0; mi < 4; mi++) ldsm_x4(a[0][mi], st0 + aoff[mi]);
#pragma unroll
        for (int nh = 0; nh < 2; nh++) ldsm_x4(b[0][nh], st0 + boff[nh]);
    }

#define MMA_ROW(buf, mi)                                                     \
    do {                                                                     \
        mma16816(acc[mi][0], a[buf][mi], b[buf][0][0], b[buf][0][2]);        \
        mma16816(acc[mi][1], a[buf][mi], b[buf][0][1], b[buf][0][3]);        \
        mma16816(acc[mi][2], a[buf][mi], b[buf][1][0], b[buf][1][2]);        \
        mma16816(acc[mi][3], a[buf][mi], b[buf][1][1], b[buf][1][3]);        \
    } while (0)

    for (int kt = 0; kt < 64; kt++) {
        const uint32_t st  = sb + (kt % STAGES) * STG;
        const uint32_t stn = sb + ((kt + 1) % STAGES) * STG;
        issue();                            // stage kt+2 -> slot (kt-1)%3
#pragma unroll
        for (int kk = 0; kk < 3; kk++) {    // R14 burst order: 6 ldsm, 16 MMA
            const int cur = kk & 1, nxt = cur ^ 1;
            const uint32_t kadd = (uint32_t)((kk + 1) * 32);
#pragma unroll
            for (int mi = 0; mi < 4; mi++) ldsm_x4(a[nxt][mi], st + aoff[mi] + kadd);
#pragma unroll
            for (int nh = 0; nh < 2; nh++) ldsm_x4(b[nxt][nh], st + boff[nh] + kadd);
            MMA_ROW(cur, 0);
            MMA_ROW(cur, 1);
            MMA_ROW(cur, 2);
            MMA_ROW(cur, 3);
        }
        {   // kk == 3 (cur = 1, nxt = 0): cover the barrier with 8 MMAs
            MMA_ROW(1, 0);
            MMA_ROW(1, 1);
            CP_WAIT(1);                     // stage kt+1 resident
            __syncthreads();
#pragma unroll
            for (int mi = 0; mi < 4; mi++) ldsm_x4(a[0][mi], stn + aoff[mi]);
#pragma unroll
            for (int nh = 0; nh < 2; nh++) ldsm_x4(b[0][nh], stn + boff[nh]);
            MMA_ROW(1, 2);
            MMA_ROW(1, 3);
        }
    }
#undef MMA_ROW

    const int r0 = lid >> 2, c0 = (lid & 3) * 2;
#pragma unroll
    for (int mi = 0; mi < 4; mi++)
#pragma unroll
        for (int ni = 0; ni < 4; ni++) {
            size_t m = m0 + wm * 64 + mi * 16 + r0;
            size_t n = n0 + wn * 32 + ni * 8 + c0;
            *(float2*)(out + m * 4096 + n) =
                make_float2(acc[mi][ni][0], acc[mi][ni][1]);
            *(float2*)(out + (m + 8) * 4096 + n) =
                make_float2(acc[mi][ni][2], acc[mi][ni][3]);
        }
}

// ---------------------------------------------------------------------------
extern "C" void kernel_launch(void* const* d_in, const int* in_sizes, int n_in,
                              void* d_out, int out_size) {
    const float* x      = (const float*)d_in[0];
    const int*   packed = (const int*)  d_in[1];
    const float* cb     = (const float*)d_in[2];
    const float* norms  = (const float*)d_in[3];
    const float* rot    = (const float*)d_in[4];
    float* out = (float*)d_out;

    cudaFuncSetAttribute(transpose_r_kernel, cudaFuncAttributeMaxDynamicSharedMemorySize, 66048);
    cudaFuncSetAttribute(prep_mma_kernel,   cudaFuncAttributeMaxDynamicSharedMemorySize, PREP_SMEM);
    cudaFuncSetAttribute(gemm_kernel,       cudaFuncAttributeMaxDynamicSharedMemorySize, GEMM_SMEM);

    convert_x_kernel<<<32768, 256>>>((const float4*)x);
    transpose_r_kernel<<<32, 256, 66048>>>(rot);
    prep_mma_kernel<<<dim3(32, 32), 256, PREP_SMEM>>>(packed, cb, norms);
    gemm_kernel<<<dim3(64, 32), 256, GEMM_SMEM>>>(out);
}

// round 17
// speedup vs baseline: 1.2215x; 1.0633x over previous
#include <cuda_runtime.h>
#include <cuda_fp16.h>
#include <cstdint>
#include <cstddef>

// ============================================================================
// TurboQuantLinear: out[t,n] = sum_k x[t,k] * W_eff[n,k]
//   W_eff[n, g*128+k] = (norms[n,g]/sqrt(128)) * sum_j codes[n,g,j]*R[g,j,k]
// sm_100 (no 'a'). ldmatrix + mma.sync m16n8k16 fp16->fp32.
// R17: GEMM frozen at the R14 schedule (measured best: gemm 672.8us,
// tensor 78.6%; R15/R16 proved any burst-splitting regresses). Only change:
// convert_x gets MLP=4 grid-stride to push HBM from 66% toward peak.
// ============================================================================

constexpr int TOKENS = 8192;
constexpr int KDIM   = 4096;
constexpr int NDIM   = 4096;
constexpr float INV_SCALE = 0.08838834764831845f; // 1/sqrt(128)

__device__ __align__(16) __half g_xh[(size_t)TOKENS * KDIM];   // 64 MB
__device__ __align__(16) __half g_wh[(size_t)NDIM * KDIM];     // 32 MB
__device__ __align__(16) __half g_rt[(size_t)32 * 128 * 128];  // 1 MB, Rt[g][k][j]

// ---- PTX helpers -----------------------------------------------------------
__device__ __forceinline__ uint32_t smem_u32(const void* p) {
    uint32_t a;
    asm("{ .reg .u64 t; cvta.to.shared.u64 t, %1; cvt.u32.u64 %0, t; }"
        : "=r"(a) : "l"(p));
    return a;
}
__device__ __forceinline__ void cp16(uint32_t s, const void* g) {
    asm volatile("cp.async.cg.shared.global [%0], [%1], 16;" :: "r"(s), "l"(g));
}
#define CP_COMMIT() asm volatile("cp.async.commit_group;" ::: "memory")
#define CP_WAIT(n)  asm volatile("cp.async.wait_group %0;" :: "n"(n) : "memory")

__device__ __forceinline__ void ldsm_x4(uint32_t (&r)[4], uint32_t addr) {
    asm volatile("ldmatrix.sync.aligned.m8n8.x4.shared.b16 {%0,%1,%2,%3}, [%4];"
        : "=r"(r[0]), "=r"(r[1]), "=r"(r[2]), "=r"(r[3]) : "r"(addr));
}
__device__ __forceinline__ void mma16816(float (&d)[4], const uint32_t (&a)[4],
                                         uint32_t b0, uint32_t b1) {
    asm volatile("mma.sync.aligned.m16n8k16.row.col.f32.f16.f16.f32 "
        "{%0,%1,%2,%3}, {%4,%5,%6,%7}, {%8,%9}, {%0,%1,%2,%3};"
        : "+f"(d[0]), "+f"(d[1]), "+f"(d[2]), "+f"(d[3])
        : "r"(a[0]), "r"(a[1]), "r"(a[2]), "r"(a[3]), "r"(b0), "r"(b1));
}
__device__ __forceinline__ uint32_t pack_h2(__half a, __half b) {
    return (uint32_t)__half_as_ushort(a) | ((uint32_t)__half_as_ushort(b) << 16);
}

// ---------------------------------------------------------------------------
// Kernel 1: x fp32 -> fp16, MLP=4 (4 consecutive float4 chunks per thread)
// ---------------------------------------------------------------------------
__global__ void __launch_bounds__(256) convert_x_kernel(const float4* __restrict__ x) {
    const size_t base = (size_t)blockIdx.x * 1024 + threadIdx.x;
    float4 v[4];
#pragma unroll
    for (int p = 0; p < 4; p++) v[p] = x[base + 256 * p];
#pragma unroll
    for (int p = 0; p < 4; p++) {
        uint2 o;
        o.x = pack_h2(__float2half_rn(v[p].x), __float2half_rn(v[p].y));
        o.y = pack_h2(__float2half_rn(v[p].z), __float2half_rn(v[p].w));
        *(uint2*)(g_xh + 4 * (base + 256 * p)) = o;
    }
}

// ---------------------------------------------------------------------------
// Kernel 2a: Rt[g][k][j] = fp16(rot[g][j][k]). One block per group.
// ---------------------------------------------------------------------------
__global__ void __launch_bounds__(256) transpose_r_kernel(const float* __restrict__ rot) {
    extern __shared__ float rs[];           // 128*129 floats = 66048 B
    const int t = threadIdx.x;
    const int g = blockIdx.x;
    const float* rg = rot + (size_t)g * 16384;
#pragma unroll 16
    for (int it = 0; it < 64; it++) {
        int idx = t + 256 * it;             // j*128 + k
        rs[(idx >> 7) * 129 + (idx & 127)] = rg[idx];
    }
    __syncthreads();
    __half* og = g_rt + (size_t)g * 16384;
#pragma unroll 16
    for (int it = 0; it < 64; it++) {
        int idx = t + 256 * it;             // k*128 + j
        int k = idx >> 7, j = idx & 127;
        og[idx] = __float2half_rn(rs[j * 129 + k]);
    }
}

// ---------------------------------------------------------------------------
// Kernel 2b: prep on tensor cores (unchanged; measured fast).
// ---------------------------------------------------------------------------
constexpr int PROWB = 272;
constexpr int PTILE = 128 * PROWB;          // 34816
constexpr int PREP_SMEM = 2 * PTILE;        // 69632

__global__ void __launch_bounds__(256, 1) prep_mma_kernel(
        const int* __restrict__ packed, const float* __restrict__ cb,
        const float* __restrict__ norms) {
    extern __shared__ __align__(128) char psm[];
    __shared__ float cbs[16];
    __shared__ float snorm[128];
    const uint32_t sb = smem_u32(psm);
    const int t = threadIdx.x, lid = t & 31, wid = t >> 5;
    const int g = blockIdx.y;
    const int row0 = blockIdx.x * 128;

    if (t < 16) cbs[t] = cb[t];
    if (t < 128) snorm[t] = norms[(size_t)(row0 + t) * 32 + g] * INV_SCALE;

#pragma unroll
    for (int p = 0; p < 8; p++) {
        int ch = t + 256 * p; int r = ch >> 4, c = ch & 15;
        cp16(sb + PTILE + (uint32_t)(r * PROWB + c * 16),
             g_rt + (size_t)g * 16384 + r * 128 + c * 8);
    }
    CP_COMMIT();
    __syncthreads();

#pragma unroll 8
    for (int it = 0; it < 32; it++) {
        int idx = t + 256 * it;
        int r = idx >> 6, ii = idx & 63;
        int v = packed[(size_t)(row0 + r) * 2048 + g * 64 + ii] & 0xFF;
        *(uint32_t*)(psm + r * PROWB + ii * 4) =
            pack_h2(__float2half_rn(cbs[v & 0xF]), __float2half_rn(cbs[(v >> 4) & 0xF]));
    }
    CP_WAIT(0);
    __syncthreads();

    const int wm = wid & 1, wn = wid >> 1;
    const int rsel = lid & 15, csel = lid >> 4;

    float acc[4][4][4];
#pragma unroll
    for (int mi = 0; mi < 4; mi++)
#pragma unroll
        for (int ni = 0; ni < 4; ni++)
#pragma unroll
            for (int q = 0; q < 4; q++) acc[mi][ni][q] = 0.f;

#pragma unroll
    for (int k16 = 0; k16 < 8; k16++) {
        uint32_t a[4][4], b[2][4];
        const uint32_t kadd = (uint32_t)(k16 * 32 + csel * 16);
#pragma unroll
        for (int mi = 0; mi < 4; mi++)
            ldsm_x4(a[mi], sb + (wm * 64 + mi * 16 + rsel) * PROWB + kadd);
#pragma unroll
        for (int nh = 0; nh < 2; nh++)
            ldsm_x4(b[nh], sb + PTILE + (wn * 32 + nh * 16 + rsel) * PROWB + kadd);
#pragma unroll
        for (int mi = 0; mi < 4; mi++)
#pragma unroll
            for (int ni = 0; ni < 4; ni++) {
                const int nh = ni >> 1, s2 = ni & 1;
                mma16816(acc[mi][ni], a[mi], b[nh][s2], b[nh][s2 + 2]);
            }
    }

    const int r0 = lid >> 2, c0 = (lid & 3) * 2;
#pragma unroll
    for (int mi = 0; mi < 4; mi++) {
        const int mloc = wm * 64 + mi * 16 + r0;
        const float s0 = snorm[mloc], s1 = snorm[mloc + 8];
#pragma unroll
        for (int ni = 0; ni < 4; ni++) {
            const int kout = wn * 32 + ni * 8 + c0;
            size_t o = (size_t)(row0 + mloc) * 4096 + g * 128 + kout;
            *(uint32_t*)(g_wh + o) =
                pack_h2(__float2half_rn(acc[mi][ni][0] * s0),
                        __float2half_rn(acc[mi][ni][1] * s0));
            *(uint32_t*)(g_wh + o + 8 * 4096) =
                pack_h2(__float2half_rn(acc[mi][ni][2] * s1),
                        __float2half_rn(acc[mi][ni][3] * s1));
        }
    }
}

// ---------------------------------------------------------------------------
// Kernel 3: GEMM — EXACT R14 schedule (do not modify).
// BM=128 BN=128 BK=64, 3 stages, 256 threads (8 warps, 2x4), warp tile
// 64x32, 2 CTAs/SM, frag double-buffering, rolling load pointers.
// ---------------------------------------------------------------------------
constexpr int STAGES = 3;
constexpr int ROWB   = 144;
constexpr int ATILEB = 128 * ROWB;          // 18432
constexpr int BTILEB = 128 * ROWB;          // 18432
constexpr int STG    = ATILEB + BTILEB;     // 36864
constexpr int GEMM_SMEM = STAGES * STG;     // 110592  (x2 CTAs = 221184)

__global__ void __launch_bounds__(256, 2) gemm_kernel(float* __restrict__ out) {
    extern __shared__ __align__(128) char smem[];
    const uint32_t sb = smem_u32(smem);
    const int tid = threadIdx.x, lid = tid & 31, wid = tid >> 5;
    const int wm = wid & 1, wn = wid >> 1;          // 2 (M) x 4 (N)
    const size_t m0 = (size_t)blockIdx.x * 128;
    const size_t n0 = (size_t)blockIdx.y * 128;

    float acc[4][4][4];
#pragma unroll
    for (int mi = 0; mi < 4; mi++)
#pragma unroll
        for (int ni = 0; ni < 4; ni++)
#pragma unroll
            for (int q = 0; q < 4; q++) acc[mi][ni][q] = 0.f;

    // rolling cp.async state
    const int lr = tid >> 3, lc = tid & 7;
    const __half* pa = g_xh + (m0 + lr) * 4096 + lc * 8;
    const __half* pb = g_wh + (n0 + lr) * 4096 + lc * 8;
    const uint32_t sA = sb + (uint32_t)(lr * ROWB + lc * 16);
    int slot = 0;
    int remaining = 64;

    auto issue = [&]() {
        if (remaining > 0) {
            const uint32_t st = sA + (uint32_t)slot * STG;
#pragma unroll
            for (int p = 0; p < 4; p++)
                cp16(st + p * (32 * ROWB), pa + (size_t)p * (32 * 4096));
#pragma unroll
            for (int p = 0; p < 4; p++)
                cp16(st + ATILEB + p * (32 * ROWB), pb + (size_t)p * (32 * 4096));
            pa += 64; pb += 64;
            remaining--;
        }
        CP_COMMIT();
        slot = (slot == STAGES - 1) ? 0 : slot + 1;
    };

    issue();        // stage 0
    issue();        // stage 1

    const int rsel = lid & 15, csel = lid >> 4;
    uint32_t aoff[4], boff[2];
#pragma unroll
    for (int mi = 0; mi < 4; mi++)
        aoff[mi] = (uint32_t)((wm * 64 + mi * 16 + rsel) * ROWB + csel * 16);
#pragma unroll
    for (int nh = 0; nh < 2; nh++)
        boff[nh] = (uint32_t)(ATILEB + (wn * 32 + nh * 16 + rsel) * ROWB + csel * 16);

    CP_WAIT(1);
    __syncthreads();

    uint32_t a[2][4][4], b[2][2][4];        // double-buffered fragments
    {
        const uint32_t st0 = sb;            // stage 0
#pragma unroll
        for (int mi = 0; mi < 4; mi++) ldsm_x4(a[0][mi], st0 + aoff[mi]);
#pragma unroll
        for (int nh = 0; nh < 2; nh++) ldsm_x4(b[0][nh], st0 + boff[nh]);
    }

    for (int kt = 0; kt < 64; kt++) {
        const uint32_t st  = sb + (kt % STAGES) * STG;
        const uint32_t stn = sb + ((kt + 1) % STAGES) * STG;
        issue();                            // stage kt+2 -> slot (kt-1)%3
#pragma unroll
        for (int kk = 0; kk < 4; kk++) {
            const int cur = kk & 1, nxt = cur ^ 1;
            if (kk < 3) {
                const uint32_t kadd = (uint32_t)((kk + 1) * 32);
#pragma unroll
                for (int mi = 0; mi < 4; mi++) ldsm_x4(a[nxt][mi], st + aoff[mi] + kadd);
#pragma unroll
                for (int nh = 0; nh < 2; nh++) ldsm_x4(b[nxt][nh], st + boff[nh] + kadd);
            } else {
                CP_WAIT(1);                 // stage kt+1 resident
                __syncthreads();
#pragma unroll
                for (int mi = 0; mi < 4; mi++) ldsm_x4(a[nxt][mi], stn + aoff[mi]);
#pragma unroll
                for (int nh = 0; nh < 2; nh++) ldsm_x4(b[nxt][nh], stn + boff[nh]);
            }
#pragma unroll
            for (int mi = 0; mi < 4; mi++)
#pragma unroll
                for (int ni = 0; ni < 4; ni++) {
                    const int nh = ni >> 1, s2 = ni & 1;
                    mma16816(acc[mi][ni], a[cur][mi], b[cur][nh][s2], b[cur][nh][s2 + 2]);
                }
        }
    }

    const int r0 = lid >> 2, c0 = (lid & 3) * 2;
#pragma unroll
    for (int mi = 0; mi < 4; mi++)
#pragma unroll
        for (int ni = 0; ni < 4; ni++) {
            size_t m = m0 + wm * 64 + mi * 16 + r0;
            size_t n = n0 + wn * 32 + ni * 8 + c0;
            *(float2*)(out + m * 4096 + n) =
                make_float2(acc[mi][ni][0], acc[mi][ni][1]);
            *(float2*)(out + (m + 8) * 4096 + n) =
                make_float2(acc[mi][ni][2], acc[mi][ni][3]);
        }
}

// ---------------------------------------------------------------------------
extern "C" void kernel_launch(void* const* d_in, const int* in_sizes, int n_in,
                              void* d_out, int out_size) {
    const float* x      = (const float*)d_in[0];
    const int*   packed = (const int*)  d_in[1];
    const float* cb     = (const float*)d_in[2];
    const float* norms  = (const float*)d_in[3];
    const float* rot    = (const float*)d_in[4];
    float* out = (float*)d_out;

    cudaFuncSetAttribute(transpose_r_kernel, cudaFuncAttributeMaxDynamicSharedMemorySize, 66048);
    cudaFuncSetAttribute(prep_mma_kernel,   cudaFuncAttributeMaxDynamicSharedMemorySize, PREP_SMEM);
    cudaFuncSetAttribute(gemm_kernel,       cudaFuncAttributeMaxDynamicSharedMemorySize, GEMM_SMEM);

    convert_x_kernel<<<8192, 256>>>((const float4*)x);
    transpose_r_kernel<<<32, 256, 66048>>>(rot);
    prep_mma_kernel<<<dim3(32, 32), 256, PREP_SMEM>>>(packed, cb, norms);
    gemm_kernel<<<dim3(64, 32), 256, GEMM_SMEM>>>(out);
}